// round 1
// baseline (speedup 1.0000x reference)
#include <cuda_runtime.h>
#include <math.h>

// Problem constants
#define T_TOK 8192      // B*S tokens
#define DIM   1024      // D
#define NE    8         // experts
#define HUP   8192      // 8*D (up output)
#define HD    4096      // 4*D (GLU half)
#define ROWS_MAX (2*T_TOK + NE*128)   // 17408 padded bucket rows max

// ---------------- device scratch (static, no allocations) ----------------
__device__ int   g_count[NE];
__device__ int   g_fill[NE];
__device__ int   g_off[NE];
__device__ int   g_total;
__device__ int   g_topk[T_TOK * 2];
__device__ float g_topw[T_TOK * 2];
__device__ int   g_row_tok[ROWS_MAX];
__device__ float g_row_w[ROWS_MAX];
__device__ int   g_row_slot[ROWS_MAX];
// h buffer: [ROWS_MAX][HUP]. After GLU, first HD cols hold act = a*gelu(g).
__device__ float g_h[142606336];              // 17408 * 8192  (~570 MB)
__device__ float g_y[16777216];               // [2][T_TOK][DIM] (~67 MB)

// ---------------- kernels ----------------

__global__ void reset_kernel() {
    int i = threadIdx.x;
    if (i < NE) { g_count[i] = 0; g_fill[i] = 0; }
}

// One warp per token: logits = x @ router_w + router_b, then top-2 + softmax.
__global__ void router_kernel(const float* __restrict__ x,
                              const float* __restrict__ rw,
                              const float* __restrict__ rb) {
    int t    = (blockIdx.x * blockDim.x + threadIdx.x) >> 5;
    int lane = threadIdx.x & 31;
    if (t >= T_TOK) return;
    const float* xr = x + (size_t)t * DIM;
    float acc[NE];
#pragma unroll
    for (int e = 0; e < NE; e++) acc[e] = 0.f;
    for (int d = lane; d < DIM; d += 32) {
        float xv = xr[d];
        const float* w = rw + d * NE;
#pragma unroll
        for (int e = 0; e < NE; e++) acc[e] += xv * __ldg(&w[e]);
    }
#pragma unroll
    for (int o = 16; o > 0; o >>= 1) {
#pragma unroll
        for (int e = 0; e < NE; e++)
            acc[e] += __shfl_xor_sync(0xffffffffu, acc[e], o);
    }
    if (lane == 0) {
        float l1 = -1e30f, l2 = -1e30f;
        int i1 = 0, i2 = 0;
#pragma unroll
        for (int e = 0; e < NE; e++) {
            float l = acc[e] + rb[e];
            if (l > l1)      { l2 = l1; i2 = i1; l1 = l; i1 = e; }
            else if (l > l2) { l2 = l; i2 = e; }
        }
        // softmax over [l1, l2] (l1 >= l2)
        float p2 = 1.f / (1.f + __expf(l1 - l2));
        // use accurate exp to be safe:
        p2 = 1.f / (1.f + expf(l1 - l2));
        float p1 = 1.f - p2;
        g_topk[2 * t + 0] = i1;  g_topw[2 * t + 0] = p1;
        g_topk[2 * t + 1] = i2;  g_topw[2 * t + 1] = p2;
        atomicAdd(&g_count[i1], 1);
        atomicAdd(&g_count[i2], 1);
    }
}

__global__ void offsets_kernel() {
    if (threadIdx.x == 0) {
        int tot = 0;
        for (int e = 0; e < NE; e++) {
            g_off[e] = tot;
            tot += ((g_count[e] + 127) >> 7) << 7;
        }
        g_total = tot;
    }
}

__global__ void scatter_kernel() {
    int t = blockIdx.x * blockDim.x + threadIdx.x;
    if (t >= T_TOK) return;
#pragma unroll
    for (int k = 0; k < 2; k++) {
        int e = g_topk[2 * t + k];
        int pos = atomicAdd(&g_fill[e], 1);
        int row = g_off[e] + pos;
        g_row_tok[row]  = t;
        g_row_w[row]    = g_topw[2 * t + k];
        g_row_slot[row] = k * T_TOK + t;
    }
}

// Up GEMM: h[row, n] = x[tok(row), :] @ up_w[e] + up_b[e]   (128x128x16 tiles)
__global__ __launch_bounds__(256) void up_gemm_kernel(const float* __restrict__ x,
                                                      const float* __restrict__ uw,
                                                      const float* __restrict__ ub) {
    int e = blockIdx.z;
    int cnt = g_count[e];
    int mt = blockIdx.y;
    if (mt * 128 >= cnt) return;
    int base = g_off[e] + mt * 128;
    int n0 = blockIdx.x * 128;
    const float* B = uw + (size_t)e * DIM * HUP;

    __shared__ float As[16 * 128];
    __shared__ float Bs[16 * 128];
    __shared__ int   toks[128];

    int tid = threadIdx.x;
    if (tid < 128)
        toks[tid] = (mt * 128 + tid < cnt) ? g_row_tok[base + tid] : -1;
    __syncthreads();

    int tx = tid & 15, ty = tid >> 4;
    float acc[8][8];
#pragma unroll
    for (int i = 0; i < 8; i++)
#pragma unroll
        for (int j = 0; j < 8; j++) acc[i][j] = 0.f;

    for (int k0 = 0; k0 < DIM; k0 += 16) {
#pragma unroll
        for (int r = 0; r < 2; r++) {
            int id = tid + r * 256;
            int m = id >> 2, k4 = id & 3;
            int tok = toks[m];
            float4 v = make_float4(0.f, 0.f, 0.f, 0.f);
            if (tok >= 0)
                v = *(const float4*)(x + (size_t)tok * DIM + k0 + k4 * 4);
            As[(k4 * 4 + 0) * 128 + m] = v.x;
            As[(k4 * 4 + 1) * 128 + m] = v.y;
            As[(k4 * 4 + 2) * 128 + m] = v.z;
            As[(k4 * 4 + 3) * 128 + m] = v.w;
        }
#pragma unroll
        for (int r = 0; r < 2; r++) {
            int id = tid + r * 256;
            int k = id >> 5, n4 = id & 31;
            float4 v = *(const float4*)(B + (size_t)(k0 + k) * HUP + n0 + n4 * 4);
            *(float4*)(&Bs[k * 128 + n4 * 4]) = v;
        }
        __syncthreads();
#pragma unroll
        for (int kk = 0; kk < 16; kk++) {
            float a[8], b[8];
#pragma unroll
            for (int i = 0; i < 8; i++) a[i] = As[kk * 128 + ty * 8 + i];
#pragma unroll
            for (int j = 0; j < 8; j++) b[j] = Bs[kk * 128 + tx * 8 + j];
#pragma unroll
            for (int i = 0; i < 8; i++)
#pragma unroll
                for (int j = 0; j < 8; j++) acc[i][j] += a[i] * b[j];
        }
        __syncthreads();
    }

    float bv[8];
#pragma unroll
    for (int j = 0; j < 8; j++)
        bv[j] = ub[(size_t)e * HUP + n0 + tx * 8 + j];
#pragma unroll
    for (int i = 0; i < 8; i++) {
        size_t ro = (size_t)(base + ty * 8 + i) * HUP + n0 + tx * 8;
        float4 v0 = make_float4(acc[i][0] + bv[0], acc[i][1] + bv[1],
                                acc[i][2] + bv[2], acc[i][3] + bv[3]);
        float4 v1 = make_float4(acc[i][4] + bv[4], acc[i][5] + bv[5],
                                acc[i][6] + bv[6], acc[i][7] + bv[7]);
        *(float4*)(&g_h[ro])     = v0;
        *(float4*)(&g_h[ro + 4]) = v1;
    }
}

__device__ __forceinline__ float gelu_exact(float v) {
    return 0.5f * v * (1.f + erff(v * 0.70710678118654752f));
}

// act[row, j] = h[row, j] * gelu(h[row, j+HD]); stored in-place at h[row, j]
__global__ void glu_kernel() {
    int total = g_total;
    int idx = blockIdx.x * blockDim.x + threadIdx.x;   // float4 index
    int row = idx >> 10;                                // HD/4 = 1024 f4 per row
    if (row >= total) return;
    int j4 = idx & 1023;
    size_t baseo = (size_t)row * HUP + j4 * 4;
    float4 a = *(float4*)(&g_h[baseo]);
    float4 g = *(float4*)(&g_h[baseo + HD]);
    a.x *= gelu_exact(g.x);
    a.y *= gelu_exact(g.y);
    a.z *= gelu_exact(g.z);
    a.w *= gelu_exact(g.w);
    *(float4*)(&g_h[baseo]) = a;
}

// Down GEMM: y[slot(row), n] = w(row) * (act[row,:] @ down_w[e] + down_b[e])
__global__ __launch_bounds__(256) void down_gemm_kernel(const float* __restrict__ dw,
                                                        const float* __restrict__ db) {
    int e = blockIdx.z;
    int cnt = g_count[e];
    int mt = blockIdx.y;
    if (mt * 128 >= cnt) return;
    int base = g_off[e] + mt * 128;
    int n0 = blockIdx.x * 128;
    const float* B = dw + (size_t)e * HD * DIM;

    __shared__ float As[16 * 128];
    __shared__ float Bs[16 * 128];

    int tid = threadIdx.x;
    int tx = tid & 15, ty = tid >> 4;
    float acc[8][8];
#pragma unroll
    for (int i = 0; i < 8; i++)
#pragma unroll
        for (int j = 0; j < 8; j++) acc[i][j] = 0.f;

    for (int k0 = 0; k0 < HD; k0 += 16) {
#pragma unroll
        for (int r = 0; r < 2; r++) {
            int id = tid + r * 256;
            int m = id >> 2, k4 = id & 3;
            float4 v = *(const float4*)(&g_h[(size_t)(base + m) * HUP + k0 + k4 * 4]);
            As[(k4 * 4 + 0) * 128 + m] = v.x;
            As[(k4 * 4 + 1) * 128 + m] = v.y;
            As[(k4 * 4 + 2) * 128 + m] = v.z;
            As[(k4 * 4 + 3) * 128 + m] = v.w;
        }
#pragma unroll
        for (int r = 0; r < 2; r++) {
            int id = tid + r * 256;
            int k = id >> 5, n4 = id & 31;
            float4 v = *(const float4*)(B + (size_t)(k0 + k) * DIM + n0 + n4 * 4);
            *(float4*)(&Bs[k * 128 + n4 * 4]) = v;
        }
        __syncthreads();
#pragma unroll
        for (int kk = 0; kk < 16; kk++) {
            float a[8], b[8];
#pragma unroll
            for (int i = 0; i < 8; i++) a[i] = As[kk * 128 + ty * 8 + i];
#pragma unroll
            for (int j = 0; j < 8; j++) b[j] = Bs[kk * 128 + tx * 8 + j];
#pragma unroll
            for (int i = 0; i < 8; i++)
#pragma unroll
                for (int j = 0; j < 8; j++) acc[i][j] += a[i] * b[j];
        }
        __syncthreads();
    }

    float bv[8];
#pragma unroll
    for (int j = 0; j < 8; j++)
        bv[j] = db[(size_t)e * DIM + n0 + tx * 8 + j];
#pragma unroll
    for (int i = 0; i < 8; i++) {
        int mg = mt * 128 + ty * 8 + i;
        if (mg >= cnt) continue;
        int row = base + ty * 8 + i;
        int slot = g_row_slot[row];
        float w = g_row_w[row];
        size_t ro = (size_t)slot * DIM + n0 + tx * 8;
        float4 v0 = make_float4(w * (acc[i][0] + bv[0]), w * (acc[i][1] + bv[1]),
                                w * (acc[i][2] + bv[2]), w * (acc[i][3] + bv[3]));
        float4 v1 = make_float4(w * (acc[i][4] + bv[4]), w * (acc[i][5] + bv[5]),
                                w * (acc[i][6] + bv[6]), w * (acc[i][7] + bv[7]));
        *(float4*)(&g_y[ro])     = v0;
        *(float4*)(&g_y[ro + 4]) = v1;
    }
}

__global__ void combine_kernel(float* __restrict__ out) {
    int idx = blockIdx.x * blockDim.x + threadIdx.x;    // float4 index
    if (idx >= T_TOK * DIM / 4) return;
    float4 a = *(float4*)(&g_y[(size_t)idx * 4]);
    float4 b = *(float4*)(&g_y[(size_t)(T_TOK * DIM) + (size_t)idx * 4]);
    a.x += b.x; a.y += b.y; a.z += b.z; a.w += b.w;
    *(float4*)(&((float4*)out)[idx]) = a;
}

// ---------------- launch ----------------
extern "C" void kernel_launch(void* const* d_in, const int* in_sizes, int n_in,
                              void* d_out, int out_size) {
    const float* x  = (const float*)d_in[0];
    const float* rw = (const float*)d_in[1];
    const float* rb = (const float*)d_in[2];
    const float* uw = (const float*)d_in[3];
    const float* ub = (const float*)d_in[4];
    const float* dw = (const float*)d_in[5];
    const float* db = (const float*)d_in[6];
    float* out = (float*)d_out;

    reset_kernel<<<1, 32>>>();
    router_kernel<<<(T_TOK * 32) / 256, 256>>>(x, rw, rb);
    offsets_kernel<<<1, 32>>>();
    scatter_kernel<<<T_TOK / 256, 256>>>();
    up_gemm_kernel<<<dim3(HUP / 128, 64, NE), 256>>>(x, uw, ub);
    glu_kernel<<<(ROWS_MAX * (HD / 4) + 255) / 256, 256>>>();
    down_gemm_kernel<<<dim3(DIM / 128, 64, NE), 256>>>(dw, db);
    combine_kernel<<<(T_TOK * DIM / 4 + 255) / 256, 256>>>(out);
}

// round 5
// speedup vs baseline: 3.0679x; 3.0679x over previous
#include <cuda_runtime.h>
#include <cuda_bf16.h>
#include <math.h>
#include <stdint.h>

// ---------------- problem constants ----------------
#define T_TOK 8192
#define DIM   1024
#define NE    8
#define HUP   8192
#define HD    4096
#define ROWS_MAX   (2*T_TOK + NE*128)     // 17408
#define NTILES_MAX (ROWS_MAX/128)         // 136

// ---------------- device scratch ----------------
__device__ int   g_count[NE];
__device__ int   g_fill[NE];
__device__ int   g_off[NE];
__device__ int   g_tile_e[NTILES_MAX];
__device__ int   g_topk[T_TOK*2];
__device__ float g_topw[T_TOK*2];
__device__ int   g_row_tok[ROWS_MAX];
__device__ float g_row_w[ROWS_MAX];
__device__ int   g_row_slot[ROWS_MAX];

__device__ __nv_bfloat16 g_xhi[T_TOK*DIM];
__device__ __nv_bfloat16 g_xlo[T_TOK*DIM];
__device__ __nv_bfloat16 g_Buph[67108864];   // [E][N=8192][K=1024]
__device__ __nv_bfloat16 g_Bupl[67108864];
__device__ __nv_bfloat16 g_Bdnh[33554432];   // [E][N=1024][K=4096]
__device__ __nv_bfloat16 g_Bdnl[33554432];
__device__ __nv_bfloat16 g_acth[71303168];   // [ROWS_MAX][4096]
__device__ __nv_bfloat16 g_actl[71303168];
__device__ float         g_y[16777216];      // [2][T_TOK][DIM]

// ---------------- PTX helpers ----------------
__device__ __forceinline__ uint32_t smem_u32(const void* p) {
    uint32_t a;
    asm("{ .reg .u64 t; cvta.to.shared.u64 t, %1; cvt.u32.u64 %0, t; }" : "=r"(a) : "l"(p));
    return a;
}
__device__ __forceinline__ void cpa16(uint32_t dst, const void* src, int zfill) {
    asm volatile("cp.async.cg.shared.global [%0], [%1], 16, %2;"
                 :: "r"(dst), "l"(src), "r"(zfill));
}
#define CP_COMMIT() asm volatile("cp.async.commit_group;")
#define CP_WAIT1()  asm volatile("cp.async.wait_group 1;")
#define CP_WAIT0()  asm volatile("cp.async.wait_group 0;")

__device__ __forceinline__ void ldsm4(uint32_t* r, uint32_t addr) {
    asm volatile("ldmatrix.sync.aligned.m8n8.x4.shared.b16 {%0,%1,%2,%3}, [%4];"
        : "=r"(r[0]), "=r"(r[1]), "=r"(r[2]), "=r"(r[3]) : "r"(addr));
}
__device__ __forceinline__ void mma16816(float* c, const uint32_t* a, const uint32_t* b) {
    asm volatile("mma.sync.aligned.m16n8k16.row.col.f32.bf16.bf16.f32 "
        "{%0,%1,%2,%3}, {%4,%5,%6,%7}, {%8,%9}, {%0,%1,%2,%3};"
        : "+f"(c[0]), "+f"(c[1]), "+f"(c[2]), "+f"(c[3])
        : "r"(a[0]), "r"(a[1]), "r"(a[2]), "r"(a[3]), "r"(b[0]), "r"(b[1]));
}
// swizzled smem tile address: 128B rows, 16B chunks, SW128 pattern
__device__ __forceinline__ uint32_t sw_addr(uint32_t tb, int row, int cc) {
    return tb + row * 128 + ((cc ^ (row & 7)) << 4);
}

#define TILE_B 16384
#define UP_STAGE (6*TILE_B)     // Ah, Al, Bah, Bal, Bgh, Bgl
#define UP_SMEM  (2*UP_STAGE)   // 196608
#define DN_STAGE (4*TILE_B)     // Ah, Al, Bh, Bl
#define DN_SMEM  (2*DN_STAGE)   // 131072

// ---------------- small kernels ----------------
__global__ void reset_kernel() {
    int i = threadIdx.x;
    if (i < NE) { g_count[i] = 0; g_fill[i] = 0; }
}

__global__ void router_kernel(const float* __restrict__ x,
                              const float* __restrict__ rw,
                              const float* __restrict__ rb) {
    int t    = (blockIdx.x * blockDim.x + threadIdx.x) >> 5;
    int lane = threadIdx.x & 31;
    if (t >= T_TOK) return;
    const float* xr = x + (size_t)t * DIM;
    float acc[NE];
#pragma unroll
    for (int e = 0; e < NE; e++) acc[e] = 0.f;
    for (int d = lane; d < DIM; d += 32) {
        float xv = xr[d];
        const float* w = rw + d * NE;
#pragma unroll
        for (int e = 0; e < NE; e++) acc[e] += xv * __ldg(&w[e]);
    }
#pragma unroll
    for (int o = 16; o > 0; o >>= 1)
#pragma unroll
        for (int e = 0; e < NE; e++)
            acc[e] += __shfl_xor_sync(0xffffffffu, acc[e], o);
    if (lane == 0) {
        float l1 = -1e30f, l2 = -1e30f;
        int i1 = 0, i2 = 0;
#pragma unroll
        for (int e = 0; e < NE; e++) {
            float l = acc[e] + rb[e];
            if (l > l1)      { l2 = l1; i2 = i1; l1 = l; i1 = e; }
            else if (l > l2) { l2 = l; i2 = e; }
        }
        float p2 = 1.f / (1.f + expf(l1 - l2));
        float p1 = 1.f - p2;
        g_topk[2*t+0] = i1;  g_topw[2*t+0] = p1;
        g_topk[2*t+1] = i2;  g_topw[2*t+1] = p2;
        atomicAdd(&g_count[i1], 1);
        atomicAdd(&g_count[i2], 1);
    }
}

__global__ void offsets_kernel() {
    if (threadIdx.x == 0) {
        int tot = 0;
        for (int e = 0; e < NE; e++) {
            g_off[e] = tot;
            int pt = (g_count[e] + 127) >> 7;
            for (int i = 0; i < pt; i++) g_tile_e[tot/128 + i] = e;
            tot += pt * 128;
        }
        for (int i = tot/128; i < NTILES_MAX; i++) g_tile_e[i] = -1;
    }
}

__global__ void scatter_kernel() {
    int t = blockIdx.x * blockDim.x + threadIdx.x;
    if (t >= T_TOK) return;
#pragma unroll
    for (int k = 0; k < 2; k++) {
        int e = g_topk[2*t+k];
        int pos = atomicAdd(&g_fill[e], 1);
        int row = g_off[e] + pos;
        g_row_tok[row]  = t;
        g_row_w[row]    = g_topw[2*t+k];
        g_row_slot[row] = k * T_TOK + t;
    }
}

// x fp32 -> hi/lo bf16
__global__ void convert_x_kernel(const float* __restrict__ x) {
    int idx = blockIdx.x * blockDim.x + threadIdx.x;       // float4 index
    if (idx >= T_TOK * DIM / 4) return;
    float4 v = *(const float4*)(x + (size_t)idx * 4);
    union { __nv_bfloat16 b[4]; uint2 u; } H, L;
    float f[4] = {v.x, v.y, v.z, v.w};
#pragma unroll
    for (int i = 0; i < 4; i++) {
        __nv_bfloat16 h = __float2bfloat16_rn(f[i]);
        H.b[i] = h;
        L.b[i] = __float2bfloat16_rn(f[i] - __bfloat162float(h));
    }
    *(uint2*)(g_xhi + (size_t)idx * 4) = H.u;
    *(uint2*)(g_xlo + (size_t)idx * 4) = L.u;
}

// transpose [K,N] fp32 -> [N,K] hi/lo bf16 (per expert via blockIdx.z)
__device__ __forceinline__ void conv_trans_core(
    const float* __restrict__ src, __nv_bfloat16* oh, __nv_bfloat16* ol, int K, int N) {
    __shared__ float t[32][33];
    int k0 = blockIdx.y * 32, n0 = blockIdx.x * 32;
    int tx = threadIdx.x, ty = threadIdx.y;
#pragma unroll
    for (int i = 0; i < 32; i += 8)
        t[ty + i][tx] = src[(size_t)(k0 + ty + i) * N + n0 + tx];
    __syncthreads();
#pragma unroll
    for (int i = 0; i < 32; i += 8) {
        float v = t[tx][ty + i];
        __nv_bfloat16 h = __float2bfloat16_rn(v);
        __nv_bfloat16 l = __float2bfloat16_rn(v - __bfloat162float(h));
        size_t o = (size_t)(n0 + ty + i) * K + k0 + tx;
        oh[o] = h;
        ol[o] = l;
    }
}
__global__ void conv_up_kernel(const float* __restrict__ uw) {
    int e = blockIdx.z;
    conv_trans_core(uw + (size_t)e * DIM * HUP,
                    g_Buph + (size_t)e * HUP * DIM,
                    g_Bupl + (size_t)e * HUP * DIM, DIM, HUP);
}
__global__ void conv_dn_kernel(const float* __restrict__ dw) {
    int e = blockIdx.z;
    conv_trans_core(dw + (size_t)e * HD * DIM,
                    g_Bdnh + (size_t)e * DIM * HD,
                    g_Bdnl + (size_t)e * DIM * HD, HD, DIM);
}

__device__ __forceinline__ float gelu_exact(float v) {
    return 0.5f * v * (1.f + erff(v * 0.70710678118654752f));
}

// ---------------- fused up GEMM + GLU (mma.sync bf16 x3) ----------------
__global__ void __launch_bounds__(256, 1)
up_gemm_mma(const float* __restrict__ ub) {
    int e = g_tile_e[blockIdx.x];
    if (e < 0) return;
    int base = blockIdx.x * 128;
    int n0a  = blockIdx.y * 128;      // a-half column block; g-half at +HD
    int tid = threadIdx.x, wid = tid >> 5, lane = tid & 31;

    extern __shared__ __align__(1024) char smraw[];
    __shared__ int toks[128];
    uint32_t sb = smem_u32(smraw);

    if (tid < 128) {
        int r = base + tid;
        toks[tid] = (r < g_off[e] + g_count[e]) ? g_row_tok[r] : -1;
    }
    __syncthreads();

    // ---- loader lambda: stage s, k0 in elements ----
    auto load_stage = [&](int s, int k0) {
        uint32_t stg = sb + s * UP_STAGE;
#pragma unroll
        for (int i = 0; i < 24; i++) {
            int ch = tid + i * 256;              // 0..6143
            int tile = ch >> 10, cid = ch & 1023;
            int row = cid >> 3, c = cid & 7;
            uint32_t dst = stg + tile * TILE_B + row * 128 + ((c ^ (row & 7)) << 4);
            int kel = k0 + c * 8;
            const __nv_bfloat16* src;
            int z = 16;
            if (tile < 2) {
                int tok = toks[row];
                if (tok < 0) { z = 0; tok = 0; }
                src = (tile == 0 ? g_xhi : g_xlo) + ((size_t)tok << 10) + kel;
            } else {
                int nrow = n0a + row + ((tile >= 4) ? HD : 0);
                const __nv_bfloat16* bp = ((tile & 1) == 0) ? g_Buph : g_Bupl;
                src = bp + ((size_t)e << 23) + ((size_t)nrow << 10) + kel;
            }
            cpa16(dst, src, z);
        }
    };

    int mb = (wid & 3) * 32;
    int nb = (wid >> 2) * 64;
    int arow = mb + (lane & 15);
    int aco  = lane >> 4;
    int q = lane >> 3;
    int brow_off = ((q >> 1) << 3) + (lane & 7);
    int bco = q & 1;

    float aacc[2][8][4], gacc[2][8][4];
#pragma unroll
    for (int i = 0; i < 2; i++)
#pragma unroll
        for (int j = 0; j < 8; j++)
#pragma unroll
            for (int r = 0; r < 4; r++) { aacc[i][j][r] = 0.f; gacc[i][j][r] = 0.f; }

    load_stage(0, 0);
    CP_COMMIT();

    const int NC = DIM / 64;   // 16
#pragma unroll 1
    for (int c = 0; c < NC; c++) {
        if (c + 1 < NC) { load_stage((c + 1) & 1, (c + 1) * 64); CP_COMMIT(); CP_WAIT1(); }
        else            { CP_WAIT0(); }
        __syncthreads();
        uint32_t tb = sb + (c & 1) * UP_STAGE;
#pragma unroll
        for (int kk = 0; kk < 4; kk++) {
            int cc = kk * 2;
            uint32_t Ah[2][4], Al[2][4];
            ldsm4(Ah[0], sw_addr(tb,              arow,      cc + aco));
            ldsm4(Ah[1], sw_addr(tb,              arow + 16, cc + aco));
            ldsm4(Al[0], sw_addr(tb + TILE_B,     arow,      cc + aco));
            ldsm4(Al[1], sw_addr(tb + TILE_B,     arow + 16, cc + aco));
#pragma unroll
            for (int jp = 0; jp < 4; jp++) {
                int brow = nb + jp * 16 + brow_off;
                uint32_t Bah[4], Bal[4], Bgh[4], Bgl[4];
                ldsm4(Bah, sw_addr(tb + 2*TILE_B, brow, cc + bco));
                ldsm4(Bal, sw_addr(tb + 3*TILE_B, brow, cc + bco));
                ldsm4(Bgh, sw_addr(tb + 4*TILE_B, brow, cc + bco));
                ldsm4(Bgl, sw_addr(tb + 5*TILE_B, brow, cc + bco));
#pragma unroll
                for (int i = 0; i < 2; i++)
#pragma unroll
                    for (int jj = 0; jj < 2; jj++) {
                        int j = jp * 2 + jj;
                        mma16816(aacc[i][j], Ah[i], Bah + jj*2);
                        mma16816(aacc[i][j], Ah[i], Bal + jj*2);
                        mma16816(aacc[i][j], Al[i], Bah + jj*2);
                        mma16816(gacc[i][j], Ah[i], Bgh + jj*2);
                        mma16816(gacc[i][j], Ah[i], Bgl + jj*2);
                        mma16816(gacc[i][j], Al[i], Bgh + jj*2);
                    }
            }
        }
        __syncthreads();
    }

    // ---- epilogue: act = (a+ba) * gelu(g+bg), hi/lo bf16 ----
    int r0 = lane >> 2, cp2 = (lane & 3) * 2;
    const float* ubp = ub + (size_t)e * HUP;
#pragma unroll
    for (int i = 0; i < 2; i++) {
        int rr0 = base + mb + i * 16 + r0;
#pragma unroll
        for (int j = 0; j < 8; j++) {
            int col  = nb + j * 8 + cp2;         // 0..127 within tile
            int gcol = n0a + col;                // column within HD
            float ba0 = __ldg(ubp + gcol),      ba1 = __ldg(ubp + gcol + 1);
            float bg0 = __ldg(ubp + HD + gcol), bg1 = __ldg(ubp + HD + gcol + 1);
            float f00 = (aacc[i][j][0] + ba0) * gelu_exact(gacc[i][j][0] + bg0);
            float f01 = (aacc[i][j][1] + ba1) * gelu_exact(gacc[i][j][1] + bg1);
            float f10 = (aacc[i][j][2] + ba0) * gelu_exact(gacc[i][j][2] + bg0);
            float f11 = (aacc[i][j][3] + ba1) * gelu_exact(gacc[i][j][3] + bg1);
            union { __nv_bfloat16 b[2]; uint32_t u; } H0, L0, H1, L1;
            __nv_bfloat16 h;
            h = __float2bfloat16_rn(f00); H0.b[0] = h; L0.b[0] = __float2bfloat16_rn(f00 - __bfloat162float(h));
            h = __float2bfloat16_rn(f01); H0.b[1] = h; L0.b[1] = __float2bfloat16_rn(f01 - __bfloat162float(h));
            h = __float2bfloat16_rn(f10); H1.b[0] = h; L1.b[0] = __float2bfloat16_rn(f10 - __bfloat162float(h));
            h = __float2bfloat16_rn(f11); H1.b[1] = h; L1.b[1] = __float2bfloat16_rn(f11 - __bfloat162float(h));
            size_t o0 = ((size_t)rr0 << 12) + gcol;
            size_t o1 = ((size_t)(rr0 + 8) << 12) + gcol;
            *(uint32_t*)(g_acth + o0) = H0.u;
            *(uint32_t*)(g_actl + o0) = L0.u;
            *(uint32_t*)(g_acth + o1) = H1.u;
            *(uint32_t*)(g_actl + o1) = L1.u;
        }
    }
}

// ---------------- down GEMM: y = w * (act @ down_w + down_b) ----------------
__global__ void __launch_bounds__(256, 1)
down_gemm_mma(const float* __restrict__ db) {
    int e = g_tile_e[blockIdx.x];
    if (e < 0) return;
    int base = blockIdx.x * 128;
    int n0   = blockIdx.y * 128;
    int tid = threadIdx.x, wid = tid >> 5, lane = tid & 31;

    extern __shared__ __align__(1024) char smraw[];
    uint32_t sb = smem_u32(smraw);

    auto load_stage = [&](int s, int k0) {
        uint32_t stg = sb + s * DN_STAGE;
#pragma unroll
        for (int i = 0; i < 16; i++) {
            int ch = tid + i * 256;              // 0..4095
            int tile = ch >> 10, cid = ch & 1023;
            int row = cid >> 3, c = cid & 7;
            uint32_t dst = stg + tile * TILE_B + row * 128 + ((c ^ (row & 7)) << 4);
            int kel = k0 + c * 8;
            const __nv_bfloat16* src;
            if (tile == 0)      src = g_acth + ((size_t)(base + row) << 12) + kel;
            else if (tile == 1) src = g_actl + ((size_t)(base + row) << 12) + kel;
            else {
                const __nv_bfloat16* bp = (tile == 2) ? g_Bdnh : g_Bdnl;
                src = bp + ((size_t)e << 22) + ((size_t)(n0 + row) << 12) + kel;
            }
            cpa16(dst, src, 16);
        }
    };

    int mb = (wid & 3) * 32;
    int nb = (wid >> 2) * 64;
    int arow = mb + (lane & 15);
    int aco  = lane >> 4;
    int q = lane >> 3;
    int brow_off = ((q >> 1) << 3) + (lane & 7);
    int bco = q & 1;

    float acc[2][8][4];
#pragma unroll
    for (int i = 0; i < 2; i++)
#pragma unroll
        for (int j = 0; j < 8; j++)
#pragma unroll
            for (int r = 0; r < 4; r++) acc[i][j][r] = 0.f;

    load_stage(0, 0);
    CP_COMMIT();

    const int NC = HD / 64;   // 64
#pragma unroll 1
    for (int c = 0; c < NC; c++) {
        if (c + 1 < NC) { load_stage((c + 1) & 1, (c + 1) * 64); CP_COMMIT(); CP_WAIT1(); }
        else            { CP_WAIT0(); }
        __syncthreads();
        uint32_t tb = sb + (c & 1) * DN_STAGE;
#pragma unroll
        for (int kk = 0; kk < 4; kk++) {
            int cc = kk * 2;
            uint32_t Ah[2][4], Al[2][4];
            ldsm4(Ah[0], sw_addr(tb,          arow,      cc + aco));
            ldsm4(Ah[1], sw_addr(tb,          arow + 16, cc + aco));
            ldsm4(Al[0], sw_addr(tb + TILE_B, arow,      cc + aco));
            ldsm4(Al[1], sw_addr(tb + TILE_B, arow + 16, cc + aco));
#pragma unroll
            for (int jp = 0; jp < 4; jp++) {
                int brow = nb + jp * 16 + brow_off;
                uint32_t Bh[4], Bl[4];
                ldsm4(Bh, sw_addr(tb + 2*TILE_B, brow, cc + bco));
                ldsm4(Bl, sw_addr(tb + 3*TILE_B, brow, cc + bco));
#pragma unroll
                for (int i = 0; i < 2; i++)
#pragma unroll
                    for (int jj = 0; jj < 2; jj++) {
                        int j = jp * 2 + jj;
                        mma16816(acc[i][j], Ah[i], Bh + jj*2);
                        mma16816(acc[i][j], Ah[i], Bl + jj*2);
                        mma16816(acc[i][j], Al[i], Bh + jj*2);
                    }
            }
        }
        __syncthreads();
    }

    // ---- epilogue: y[slot] = w * (acc + bias) ----
    int r0 = lane >> 2, cp2 = (lane & 3) * 2;
    int limit = g_off[e] + g_count[e];
    const float* dbp = db + (size_t)e * DIM + n0;
#pragma unroll
    for (int i = 0; i < 2; i++) {
        int rr0 = base + mb + i * 16 + r0;
        int rr1 = rr0 + 8;
        int   s0 = 0, s1 = 0;
        float w0 = 0.f, w1 = 0.f;
        bool v0 = rr0 < limit, v1 = rr1 < limit;
        if (v0) { s0 = g_row_slot[rr0]; w0 = g_row_w[rr0]; }
        if (v1) { s1 = g_row_slot[rr1]; w1 = g_row_w[rr1]; }
#pragma unroll
        for (int j = 0; j < 8; j++) {
            int col = nb + j * 8 + cp2;
            float b0 = __ldg(dbp + col), b1 = __ldg(dbp + col + 1);
            if (v0) {
                float2 v = make_float2(w0 * (acc[i][j][0] + b0), w0 * (acc[i][j][1] + b1));
                *(float2*)(&g_y[(size_t)s0 * DIM + n0 + col]) = v;
            }
            if (v1) {
                float2 v = make_float2(w1 * (acc[i][j][2] + b0), w1 * (acc[i][j][3] + b1));
                *(float2*)(&g_y[(size_t)s1 * DIM + n0 + col]) = v;
            }
        }
    }
}

__global__ void combine_kernel(float* __restrict__ out) {
    int idx = blockIdx.x * blockDim.x + threadIdx.x;    // float4 index
    if (idx >= T_TOK * DIM / 4) return;
    float4 a = *(float4*)(&g_y[(size_t)idx * 4]);
    float4 b = *(float4*)(&g_y[(size_t)(T_TOK * DIM) + (size_t)idx * 4]);
    a.x += b.x; a.y += b.y; a.z += b.z; a.w += b.w;
    ((float4*)out)[idx] = a;
}

// ---------------- launch ----------------
extern "C" void kernel_launch(void* const* d_in, const int* in_sizes, int n_in,
                              void* d_out, int out_size) {
    const float* x  = (const float*)d_in[0];
    const float* rw = (const float*)d_in[1];
    const float* rb = (const float*)d_in[2];
    const float* uw = (const float*)d_in[3];
    const float* ub = (const float*)d_in[4];
    const float* dw = (const float*)d_in[5];
    const float* db = (const float*)d_in[6];
    float* out = (float*)d_out;

    cudaFuncSetAttribute(up_gemm_mma,   cudaFuncAttributeMaxDynamicSharedMemorySize, UP_SMEM);
    cudaFuncSetAttribute(down_gemm_mma, cudaFuncAttributeMaxDynamicSharedMemorySize, DN_SMEM);

    reset_kernel<<<1, 32>>>();
    router_kernel<<<(T_TOK * 32) / 256, 256>>>(x, rw, rb);
    offsets_kernel<<<1, 32>>>();
    scatter_kernel<<<T_TOK / 256, 256>>>();

    convert_x_kernel<<<(T_TOK * DIM / 4 + 255) / 256, 256>>>(x);
    conv_up_kernel<<<dim3(HUP / 32, DIM / 32, NE), dim3(32, 8)>>>(uw);
    conv_dn_kernel<<<dim3(DIM / 32, HD / 32, NE), dim3(32, 8)>>>(dw);

    up_gemm_mma<<<dim3(NTILES_MAX, HD / 128), 256, UP_SMEM>>>(ub);
    down_gemm_mma<<<dim3(NTILES_MAX, DIM / 128), 256, DN_SMEM>>>(db);
    combine_kernel<<<(T_TOK * DIM / 4 + 255) / 256, 256>>>(out);
}

// round 6
// speedup vs baseline: 4.1491x; 1.3524x over previous
#include <cuda_runtime.h>
#include <cuda_fp16.h>
#include <math.h>
#include <stdint.h>

// ---------------- problem constants ----------------
#define T_TOK 8192
#define DIM   1024
#define NE    8
#define HUP   8192
#define HD    4096
#define ROWS_MAX   (2*T_TOK + NE*128)     // 17408
#define NTILES_MAX (ROWS_MAX/128)         // 136

// ---------------- device scratch ----------------
__device__ int   g_count[NE];
__device__ int   g_fill[NE];
__device__ int   g_off[NE];
__device__ int   g_tile_e[NTILES_MAX];
__device__ int   g_topk[T_TOK*2];
__device__ float g_topw[T_TOK*2];
__device__ int   g_row_tok[ROWS_MAX];
__device__ float g_row_w[ROWS_MAX];
__device__ int   g_row_slot[ROWS_MAX];

__device__ __half g_xh[T_TOK*DIM];
__device__ __half g_Buph[67108864];   // [E][N=8192][K=1024] fp16 hi
__device__ __half g_Bupl[67108864];   // fp16 lo
__device__ __half g_Bdnh[33554432];   // [E][N=1024][K=4096]
__device__ __half g_Bdnl[33554432];
__device__ __half g_act[71303168];    // [ROWS_MAX][4096] fp16
__device__ float  g_y[16777216];      // [2][T_TOK][DIM]

// ---------------- PTX helpers ----------------
__device__ __forceinline__ uint32_t smem_u32(const void* p) {
    uint32_t a;
    asm("{ .reg .u64 t; cvta.to.shared.u64 t, %1; cvt.u32.u64 %0, t; }" : "=r"(a) : "l"(p));
    return a;
}
__device__ __forceinline__ void cpa16(uint32_t dst, const void* src, int zfill) {
    asm volatile("cp.async.cg.shared.global [%0], [%1], 16, %2;"
                 :: "r"(dst), "l"(src), "r"(zfill));
}
#define CP_COMMIT() asm volatile("cp.async.commit_group;")
#define CP_WAIT1()  asm volatile("cp.async.wait_group 1;")
#define CP_WAIT0()  asm volatile("cp.async.wait_group 0;")

__device__ __forceinline__ void ldsm4(uint32_t* r, uint32_t addr) {
    asm volatile("ldmatrix.sync.aligned.m8n8.x4.shared.b16 {%0,%1,%2,%3}, [%4];"
        : "=r"(r[0]), "=r"(r[1]), "=r"(r[2]), "=r"(r[3]) : "r"(addr));
}
__device__ __forceinline__ void mma16816(float* c, const uint32_t* a, const uint32_t* b) {
    asm volatile("mma.sync.aligned.m16n8k16.row.col.f32.f16.f16.f32 "
        "{%0,%1,%2,%3}, {%4,%5,%6,%7}, {%8,%9}, {%0,%1,%2,%3};"
        : "+f"(c[0]), "+f"(c[1]), "+f"(c[2]), "+f"(c[3])
        : "r"(a[0]), "r"(a[1]), "r"(a[2]), "r"(a[3]), "r"(b[0]), "r"(b[1]));
}
__device__ __forceinline__ uint32_t sw_addr(uint32_t tb, int row, int cc) {
    return tb + row * 128 + ((cc ^ (row & 7)) << 4);
}

#define TILE_B 16384
#define UP_STAGE (5*TILE_B)     // A, Bah, Bal, Bgh, Bgl
#define UP_SMEM  (2*UP_STAGE)   // 163840
#define DN_STAGE (3*TILE_B)     // A, Bh, Bl
#define DN_SMEM  (2*DN_STAGE)   // 98304

// ---------------- small kernels ----------------
__global__ void reset_kernel() {
    int i = threadIdx.x;
    if (i < NE) { g_count[i] = 0; g_fill[i] = 0; }
}

__global__ void router_kernel(const float* __restrict__ x,
                              const float* __restrict__ rw,
                              const float* __restrict__ rb) {
    int t    = (blockIdx.x * blockDim.x + threadIdx.x) >> 5;
    int lane = threadIdx.x & 31;
    if (t >= T_TOK) return;
    const float* xr = x + (size_t)t * DIM;
    float acc[NE];
#pragma unroll
    for (int e = 0; e < NE; e++) acc[e] = 0.f;
    for (int d = lane; d < DIM; d += 32) {
        float xv = xr[d];
        const float* w = rw + d * NE;
#pragma unroll
        for (int e = 0; e < NE; e++) acc[e] += xv * __ldg(&w[e]);
    }
#pragma unroll
    for (int o = 16; o > 0; o >>= 1)
#pragma unroll
        for (int e = 0; e < NE; e++)
            acc[e] += __shfl_xor_sync(0xffffffffu, acc[e], o);
    if (lane == 0) {
        float l1 = -1e30f, l2 = -1e30f;
        int i1 = 0, i2 = 0;
#pragma unroll
        for (int e = 0; e < NE; e++) {
            float l = acc[e] + rb[e];
            if (l > l1)      { l2 = l1; i2 = i1; l1 = l; i1 = e; }
            else if (l > l2) { l2 = l; i2 = e; }
        }
        float p2 = 1.f / (1.f + expf(l1 - l2));
        float p1 = 1.f - p2;
        g_topk[2*t+0] = i1;  g_topw[2*t+0] = p1;
        g_topk[2*t+1] = i2;  g_topw[2*t+1] = p2;
        atomicAdd(&g_count[i1], 1);
        atomicAdd(&g_count[i2], 1);
    }
}

__global__ void offsets_kernel() {
    if (threadIdx.x == 0) {
        int tot = 0;
        for (int e = 0; e < NE; e++) {
            g_off[e] = tot;
            int pt = (g_count[e] + 127) >> 7;
            for (int i = 0; i < pt; i++) g_tile_e[tot/128 + i] = e;
            tot += pt * 128;
        }
        for (int i = tot/128; i < NTILES_MAX; i++) g_tile_e[i] = -1;
    }
}

__global__ void scatter_kernel() {
    int t = blockIdx.x * blockDim.x + threadIdx.x;
    if (t >= T_TOK) return;
#pragma unroll
    for (int k = 0; k < 2; k++) {
        int e = g_topk[2*t+k];
        int pos = atomicAdd(&g_fill[e], 1);
        int row = g_off[e] + pos;
        g_row_tok[row]  = t;
        g_row_w[row]    = g_topw[2*t+k];
        g_row_slot[row] = k * T_TOK + t;
    }
}

// x fp32 -> single fp16
__global__ void convert_x_kernel(const float* __restrict__ x) {
    int idx = blockIdx.x * blockDim.x + threadIdx.x;       // float4 index
    if (idx >= T_TOK * DIM / 4) return;
    float4 v = *(const float4*)(x + (size_t)idx * 4);
    union { __half h[4]; uint2 u; } H;
    H.h[0] = __float2half_rn(v.x);
    H.h[1] = __float2half_rn(v.y);
    H.h[2] = __float2half_rn(v.z);
    H.h[3] = __float2half_rn(v.w);
    *(uint2*)(g_xh + (size_t)idx * 4) = H.u;
}

// transpose [K,N] fp32 -> [N,K] fp16 hi/lo (per expert via blockIdx.z)
__device__ __forceinline__ void conv_trans_core(
    const float* __restrict__ src, __half* oh, __half* ol, int K, int N) {
    __shared__ float t[32][33];
    int k0 = blockIdx.y * 32, n0 = blockIdx.x * 32;
    int tx = threadIdx.x, ty = threadIdx.y;
#pragma unroll
    for (int i = 0; i < 32; i += 8)
        t[ty + i][tx] = src[(size_t)(k0 + ty + i) * N + n0 + tx];
    __syncthreads();
#pragma unroll
    for (int i = 0; i < 32; i += 8) {
        float v = t[tx][ty + i];
        __half h = __float2half_rn(v);
        __half l = __float2half_rn(v - __half2float(h));
        size_t o = (size_t)(n0 + ty + i) * K + k0 + tx;
        oh[o] = h;
        ol[o] = l;
    }
}
__global__ void conv_up_kernel(const float* __restrict__ uw) {
    int e = blockIdx.z;
    conv_trans_core(uw + (size_t)e * DIM * HUP,
                    g_Buph + (size_t)e * HUP * DIM,
                    g_Bupl + (size_t)e * HUP * DIM, DIM, HUP);
}
__global__ void conv_dn_kernel(const float* __restrict__ dw) {
    int e = blockIdx.z;
    conv_trans_core(dw + (size_t)e * HD * DIM,
                    g_Bdnh + (size_t)e * DIM * HD,
                    g_Bdnl + (size_t)e * DIM * HD, HD, DIM);
}

__device__ __forceinline__ float gelu_exact(float v) {
    return 0.5f * v * (1.f + erff(v * 0.70710678118654752f));
}

// ---------------- fused up GEMM + GLU (fp16, W split, 2 passes) ----------------
// 512 threads, warp grid 4(m)x4(n); per warp 32x32 of each half.
__global__ void __launch_bounds__(512, 1)
up_gemm_mma(const float* __restrict__ ub) {
    int e = g_tile_e[blockIdx.x];
    if (e < 0) return;
    int base = blockIdx.x * 128;
    int n0a  = blockIdx.y * 128;      // a-half column block; g-half at +HD
    int tid = threadIdx.x, wid = tid >> 5, lane = tid & 31;

    extern __shared__ __align__(1024) char smraw[];
    __shared__ int toks[128];
    uint32_t sb = smem_u32(smraw);

    if (tid < 128) {
        int r = base + tid;
        toks[tid] = (r < g_off[e] + g_count[e]) ? g_row_tok[r] : -1;
    }
    __syncthreads();

    // tiles: 0=A(x fp16), 1=Bah, 2=Bal, 3=Bgh, 4=Bgl
    auto load_stage = [&](int s, int k0) {
        uint32_t stg = sb + s * UP_STAGE;
#pragma unroll
        for (int i = 0; i < 10; i++) {
            int ch = tid + i * 512;              // 0..5119
            int tile = ch >> 10, cid = ch & 1023;
            int row = cid >> 3, c = cid & 7;
            uint32_t dst = stg + tile * TILE_B + row * 128 + ((c ^ (row & 7)) << 4);
            int kel = k0 + c * 8;
            const __half* src;
            int z = 16;
            if (tile == 0) {
                int tok = toks[row];
                if (tok < 0) { z = 0; tok = 0; }
                src = g_xh + ((size_t)tok << 10) + kel;
            } else {
                int nrow = n0a + row + ((tile >= 3) ? HD : 0);
                const __half* bp = (tile & 1) ? g_Buph : g_Bupl;   // 1,3 -> hi; 2,4 -> lo
                src = bp + ((size_t)e << 23) + ((size_t)nrow << 10) + kel;
            }
            cpa16(dst, src, z);
        }
    };

    int mb = (wid & 3) * 32;
    int nb = (wid >> 2) * 32;
    int arow = mb + (lane & 15);
    int aco  = lane >> 4;
    int q = lane >> 3;
    int brow_off = ((q >> 1) << 3) + (lane & 7);
    int bco = q & 1;

    float aacc[2][4][4], gacc[2][4][4];
#pragma unroll
    for (int i = 0; i < 2; i++)
#pragma unroll
        for (int j = 0; j < 4; j++)
#pragma unroll
            for (int r = 0; r < 4; r++) { aacc[i][j][r] = 0.f; gacc[i][j][r] = 0.f; }

    load_stage(0, 0);
    CP_COMMIT();

    const int NC = DIM / 64;   // 16
#pragma unroll 1
    for (int c = 0; c < NC; c++) {
        if (c + 1 < NC) { load_stage((c + 1) & 1, (c + 1) * 64); CP_COMMIT(); CP_WAIT1(); }
        else            { CP_WAIT0(); }
        __syncthreads();
        uint32_t tb = sb + (c & 1) * UP_STAGE;
#pragma unroll
        for (int kk = 0; kk < 4; kk++) {
            int cc = kk * 2;
            uint32_t A2[2][4];
            ldsm4(A2[0], sw_addr(tb, arow,      cc + aco));
            ldsm4(A2[1], sw_addr(tb, arow + 16, cc + aco));
#pragma unroll
            for (int jp = 0; jp < 2; jp++) {
                int brow = nb + jp * 16 + brow_off;
                uint32_t Bah[4], Bal[4], Bgh[4], Bgl[4];
                ldsm4(Bah, sw_addr(tb + 1*TILE_B, brow, cc + bco));
                ldsm4(Bal, sw_addr(tb + 2*TILE_B, brow, cc + bco));
                ldsm4(Bgh, sw_addr(tb + 3*TILE_B, brow, cc + bco));
                ldsm4(Bgl, sw_addr(tb + 4*TILE_B, brow, cc + bco));
#pragma unroll
                for (int i = 0; i < 2; i++)
#pragma unroll
                    for (int jj = 0; jj < 2; jj++) {
                        int j = jp * 2 + jj;
                        mma16816(aacc[i][j], A2[i], Bah + jj*2);
                        mma16816(aacc[i][j], A2[i], Bal + jj*2);
                        mma16816(gacc[i][j], A2[i], Bgh + jj*2);
                        mma16816(gacc[i][j], A2[i], Bgl + jj*2);
                    }
            }
        }
        __syncthreads();
    }

    // ---- epilogue: act = (a+ba) * gelu(g+bg) -> fp16 ----
    int r0 = lane >> 2, cp2 = (lane & 3) * 2;
    const float* ubp = ub + (size_t)e * HUP;
#pragma unroll
    for (int i = 0; i < 2; i++) {
        int rr0 = base + mb + i * 16 + r0;
#pragma unroll
        for (int j = 0; j < 4; j++) {
            int col  = nb + j * 8 + cp2;
            int gcol = n0a + col;
            float ba0 = __ldg(ubp + gcol),      ba1 = __ldg(ubp + gcol + 1);
            float bg0 = __ldg(ubp + HD + gcol), bg1 = __ldg(ubp + HD + gcol + 1);
            float f00 = (aacc[i][j][0] + ba0) * gelu_exact(gacc[i][j][0] + bg0);
            float f01 = (aacc[i][j][1] + ba1) * gelu_exact(gacc[i][j][1] + bg1);
            float f10 = (aacc[i][j][2] + ba0) * gelu_exact(gacc[i][j][2] + bg0);
            float f11 = (aacc[i][j][3] + ba1) * gelu_exact(gacc[i][j][3] + bg1);
            union { __half h[2]; uint32_t u; } P0, P1;
            P0.h[0] = __float2half_rn(f00); P0.h[1] = __float2half_rn(f01);
            P1.h[0] = __float2half_rn(f10); P1.h[1] = __float2half_rn(f11);
            *(uint32_t*)(g_act + (((size_t)rr0)     << 12) + gcol) = P0.u;
            *(uint32_t*)(g_act + (((size_t)rr0 + 8) << 12) + gcol) = P1.u;
        }
    }
}

// ---------------- down GEMM: y = w * (act @ down_w + down_b) ----------------
__global__ void __launch_bounds__(512, 1)
down_gemm_mma(const float* __restrict__ db) {
    int e = g_tile_e[blockIdx.x];
    if (e < 0) return;
    int base = blockIdx.x * 128;
    int n0   = blockIdx.y * 128;
    int tid = threadIdx.x, wid = tid >> 5, lane = tid & 31;

    extern __shared__ __align__(1024) char smraw[];
    uint32_t sb = smem_u32(smraw);

    // tiles: 0=A(act), 1=Bh, 2=Bl
    auto load_stage = [&](int s, int k0) {
        uint32_t stg = sb + s * DN_STAGE;
#pragma unroll
        for (int i = 0; i < 6; i++) {
            int ch = tid + i * 512;              // 0..3071
            int tile = ch >> 10, cid = ch & 1023;
            int row = cid >> 3, c = cid & 7;
            uint32_t dst = stg + tile * TILE_B + row * 128 + ((c ^ (row & 7)) << 4);
            int kel = k0 + c * 8;
            const __half* src;
            if (tile == 0)      src = g_act + ((size_t)(base + row) << 12) + kel;
            else {
                const __half* bp = (tile == 1) ? g_Bdnh : g_Bdnl;
                src = bp + ((size_t)e << 22) + ((size_t)(n0 + row) << 12) + kel;
            }
            cpa16(dst, src, 16);
        }
    };

    int mb = (wid & 3) * 32;
    int nb = (wid >> 2) * 32;
    int arow = mb + (lane & 15);
    int aco  = lane >> 4;
    int q = lane >> 3;
    int brow_off = ((q >> 1) << 3) + (lane & 7);
    int bco = q & 1;

    float acc[2][4][4];
#pragma unroll
    for (int i = 0; i < 2; i++)
#pragma unroll
        for (int j = 0; j < 4; j++)
#pragma unroll
            for (int r = 0; r < 4; r++) acc[i][j][r] = 0.f;

    load_stage(0, 0);
    CP_COMMIT();

    const int NC = HD / 64;   // 64
#pragma unroll 1
    for (int c = 0; c < NC; c++) {
        if (c + 1 < NC) { load_stage((c + 1) & 1, (c + 1) * 64); CP_COMMIT(); CP_WAIT1(); }
        else            { CP_WAIT0(); }
        __syncthreads();
        uint32_t tb = sb + (c & 1) * DN_STAGE;
#pragma unroll
        for (int kk = 0; kk < 4; kk++) {
            int cc = kk * 2;
            uint32_t A2[2][4];
            ldsm4(A2[0], sw_addr(tb, arow,      cc + aco));
            ldsm4(A2[1], sw_addr(tb, arow + 16, cc + aco));
#pragma unroll
            for (int jp = 0; jp < 2; jp++) {
                int brow = nb + jp * 16 + brow_off;
                uint32_t Bh[4], Bl[4];
                ldsm4(Bh, sw_addr(tb + 1*TILE_B, brow, cc + bco));
                ldsm4(Bl, sw_addr(tb + 2*TILE_B, brow, cc + bco));
#pragma unroll
                for (int i = 0; i < 2; i++)
#pragma unroll
                    for (int jj = 0; jj < 2; jj++) {
                        int j = jp * 2 + jj;
                        mma16816(acc[i][j], A2[i], Bh + jj*2);
                        mma16816(acc[i][j], A2[i], Bl + jj*2);
                    }
            }
        }
        __syncthreads();
    }

    // ---- epilogue: y[slot] = w * (acc + bias) ----
    int r0 = lane >> 2, cp2 = (lane & 3) * 2;
    int limit = g_off[e] + g_count[e];
    const float* dbp = db + (size_t)e * DIM + n0;
#pragma unroll
    for (int i = 0; i < 2; i++) {
        int rr0 = base + mb + i * 16 + r0;
        int rr1 = rr0 + 8;
        int   s0 = 0, s1 = 0;
        float w0 = 0.f, w1 = 0.f;
        bool v0 = rr0 < limit, v1 = rr1 < limit;
        if (v0) { s0 = g_row_slot[rr0]; w0 = g_row_w[rr0]; }
        if (v1) { s1 = g_row_slot[rr1]; w1 = g_row_w[rr1]; }
#pragma unroll
        for (int j = 0; j < 4; j++) {
            int col = nb + j * 8 + cp2;
            float b0 = __ldg(dbp + col), b1 = __ldg(dbp + col + 1);
            if (v0) {
                float2 v = make_float2(w0 * (acc[i][j][0] + b0), w0 * (acc[i][j][1] + b1));
                *(float2*)(&g_y[(size_t)s0 * DIM + n0 + col]) = v;
            }
            if (v1) {
                float2 v = make_float2(w1 * (acc[i][j][2] + b0), w1 * (acc[i][j][3] + b1));
                *(float2*)(&g_y[(size_t)s1 * DIM + n0 + col]) = v;
            }
        }
    }
}

__global__ void combine_kernel(float* __restrict__ out) {
    int idx = blockIdx.x * blockDim.x + threadIdx.x;    // float4 index
    if (idx >= T_TOK * DIM / 4) return;
    float4 a = *(float4*)(&g_y[(size_t)idx * 4]);
    float4 b = *(float4*)(&g_y[(size_t)(T_TOK * DIM) + (size_t)idx * 4]);
    a.x += b.x; a.y += b.y; a.z += b.z; a.w += b.w;
    ((float4*)out)[idx] = a;
}

// ---------------- launch ----------------
extern "C" void kernel_launch(void* const* d_in, const int* in_sizes, int n_in,
                              void* d_out, int out_size) {
    const float* x  = (const float*)d_in[0];
    const float* rw = (const float*)d_in[1];
    const float* rb = (const float*)d_in[2];
    const float* uw = (const float*)d_in[3];
    const float* ub = (const float*)d_in[4];
    const float* dw = (const float*)d_in[5];
    const float* db = (const float*)d_in[6];
    float* out = (float*)d_out;

    cudaFuncSetAttribute(up_gemm_mma,   cudaFuncAttributeMaxDynamicSharedMemorySize, UP_SMEM);
    cudaFuncSetAttribute(down_gemm_mma, cudaFuncAttributeMaxDynamicSharedMemorySize, DN_SMEM);

    reset_kernel<<<1, 32>>>();
    router_kernel<<<(T_TOK * 32) / 256, 256>>>(x, rw, rb);
    offsets_kernel<<<1, 32>>>();
    scatter_kernel<<<T_TOK / 256, 256>>>();

    convert_x_kernel<<<(T_TOK * DIM / 4 + 255) / 256, 256>>>(x);
    conv_up_kernel<<<dim3(HUP / 32, DIM / 32, NE), dim3(32, 8)>>>(uw);
    conv_dn_kernel<<<dim3(DIM / 32, HD / 32, NE), dim3(32, 8)>>>(dw);

    up_gemm_mma<<<dim3(NTILES_MAX, HD / 128), 512, UP_SMEM>>>(ub);
    down_gemm_mma<<<dim3(NTILES_MAX, DIM / 128), 512, DN_SMEM>>>(db);
    combine_kernel<<<(T_TOK * DIM / 4 + 255) / 256, 256>>>(out);
}

// round 7
// speedup vs baseline: 6.6282x; 1.5975x over previous
#include <cuda_runtime.h>
#include <cuda_fp16.h>
#include <math.h>
#include <stdint.h>

// ---------------- problem constants ----------------
#define T_TOK 8192
#define DIM   1024
#define NE    8
#define HUP   8192
#define HD    4096
#define ROWS_MAX   (2*T_TOK + NE*128)     // 17408
#define NTILES_MAX (ROWS_MAX/128)         // 136

// ---------------- device scratch ----------------
__device__ int   g_count[NE];
__device__ int   g_fill[NE];
__device__ int   g_off[NE];
__device__ int   g_tile_e[NTILES_MAX];
__device__ int   g_topk[T_TOK*2];
__device__ float g_topw[T_TOK*2];
__device__ int   g_row_tok[ROWS_MAX];
__device__ float g_row_w[ROWS_MAX];
__device__ int   g_row_slot[ROWS_MAX];

__device__ __half g_xh[T_TOK*DIM];
__device__ __half g_Bup[67108864];    // [E][N=8192][K=1024] fp16
__device__ __half g_Bdn[33554432];    // [E][N=1024][K=4096] fp16
__device__ __half g_act[71303168];    // [ROWS_MAX][4096] fp16
__device__ float  g_y[16777216];      // [2][T_TOK][DIM]

// ---------------- PTX helpers ----------------
__device__ __forceinline__ uint32_t smem_u32(const void* p) {
    uint32_t a;
    asm("{ .reg .u64 t; cvta.to.shared.u64 t, %1; cvt.u32.u64 %0, t; }" : "=r"(a) : "l"(p));
    return a;
}
__device__ __forceinline__ void cpa16(uint32_t dst, const void* src, int zfill) {
    asm volatile("cp.async.cg.shared.global [%0], [%1], 16, %2;"
                 :: "r"(dst), "l"(src), "r"(zfill));
}
#define CP_COMMIT() asm volatile("cp.async.commit_group;")
#define CP_WAIT1()  asm volatile("cp.async.wait_group 1;")
#define CP_WAIT0()  asm volatile("cp.async.wait_group 0;")

__device__ __forceinline__ void ldsm4(uint32_t* r, uint32_t addr) {
    asm volatile("ldmatrix.sync.aligned.m8n8.x4.shared.b16 {%0,%1,%2,%3}, [%4];"
        : "=r"(r[0]), "=r"(r[1]), "=r"(r[2]), "=r"(r[3]) : "r"(addr));
}
__device__ __forceinline__ void mma16816(float* c, const uint32_t* a, const uint32_t* b) {
    asm volatile("mma.sync.aligned.m16n8k16.row.col.f32.f16.f16.f32 "
        "{%0,%1,%2,%3}, {%4,%5,%6,%7}, {%8,%9}, {%0,%1,%2,%3};"
        : "+f"(c[0]), "+f"(c[1]), "+f"(c[2]), "+f"(c[3])
        : "r"(a[0]), "r"(a[1]), "r"(a[2]), "r"(a[3]), "r"(b[0]), "r"(b[1]));
}
__device__ __forceinline__ uint32_t sw_addr(uint32_t tb, int row, int cc) {
    return tb + row * 128 + ((cc ^ (row & 7)) << 4);
}

#define TILE_B 16384
#define UP_STAGE (3*TILE_B)     // A, Ba, Bg
#define UP_SMEM  (2*UP_STAGE)   // 98304
#define DN_STAGE (2*TILE_B)     // A, B
#define DN_SMEM  (2*DN_STAGE)   // 65536

// ---------------- small kernels ----------------
__global__ void reset_kernel() {
    int i = threadIdx.x;
    if (i < NE) { g_count[i] = 0; g_fill[i] = 0; }
}

__global__ void router_kernel(const float* __restrict__ x,
                              const float* __restrict__ rw,
                              const float* __restrict__ rb) {
    int t    = (blockIdx.x * blockDim.x + threadIdx.x) >> 5;
    int lane = threadIdx.x & 31;
    if (t >= T_TOK) return;
    const float* xr = x + (size_t)t * DIM;
    float acc[NE];
#pragma unroll
    for (int e = 0; e < NE; e++) acc[e] = 0.f;
    for (int d = lane; d < DIM; d += 32) {
        float xv = xr[d];
        const float* w = rw + d * NE;
#pragma unroll
        for (int e = 0; e < NE; e++) acc[e] += xv * __ldg(&w[e]);
    }
#pragma unroll
    for (int o = 16; o > 0; o >>= 1)
#pragma unroll
        for (int e = 0; e < NE; e++)
            acc[e] += __shfl_xor_sync(0xffffffffu, acc[e], o);
    if (lane == 0) {
        float l1 = -1e30f, l2 = -1e30f;
        int i1 = 0, i2 = 0;
#pragma unroll
        for (int e = 0; e < NE; e++) {
            float l = acc[e] + rb[e];
            if (l > l1)      { l2 = l1; i2 = i1; l1 = l; i1 = e; }
            else if (l > l2) { l2 = l; i2 = e; }
        }
        float p2 = 1.f / (1.f + expf(l1 - l2));
        float p1 = 1.f - p2;
        g_topk[2*t+0] = i1;  g_topw[2*t+0] = p1;
        g_topk[2*t+1] = i2;  g_topw[2*t+1] = p2;
        atomicAdd(&g_count[i1], 1);
        atomicAdd(&g_count[i2], 1);
    }
}

__global__ void offsets_kernel() {
    if (threadIdx.x == 0) {
        int tot = 0;
        for (int e = 0; e < NE; e++) {
            g_off[e] = tot;
            int pt = (g_count[e] + 127) >> 7;
            for (int i = 0; i < pt; i++) g_tile_e[tot/128 + i] = e;
            tot += pt * 128;
        }
        for (int i = tot/128; i < NTILES_MAX; i++) g_tile_e[i] = -1;
    }
}

__global__ void scatter_kernel() {
    int t = blockIdx.x * blockDim.x + threadIdx.x;
    if (t >= T_TOK) return;
#pragma unroll
    for (int k = 0; k < 2; k++) {
        int e = g_topk[2*t+k];
        int pos = atomicAdd(&g_fill[e], 1);
        int row = g_off[e] + pos;
        g_row_tok[row]  = t;
        g_row_w[row]    = g_topw[2*t+k];
        g_row_slot[row] = k * T_TOK + t;
    }
}

// x fp32 -> fp16
__global__ void convert_x_kernel(const float* __restrict__ x) {
    int idx = blockIdx.x * blockDim.x + threadIdx.x;       // float4 index
    if (idx >= T_TOK * DIM / 4) return;
    float4 v = *(const float4*)(x + (size_t)idx * 4);
    union { __half h[4]; uint2 u; } H;
    H.h[0] = __float2half_rn(v.x);
    H.h[1] = __float2half_rn(v.y);
    H.h[2] = __float2half_rn(v.z);
    H.h[3] = __float2half_rn(v.w);
    *(uint2*)(g_xh + (size_t)idx * 4) = H.u;
}

// transpose [K,N] fp32 -> [N,K] fp16 (per expert via blockIdx.z)
__device__ __forceinline__ void conv_trans_core(
    const float* __restrict__ src, __half* oh, int K, int N) {
    __shared__ float t[32][33];
    int k0 = blockIdx.y * 32, n0 = blockIdx.x * 32;
    int tx = threadIdx.x, ty = threadIdx.y;
#pragma unroll
    for (int i = 0; i < 32; i += 8)
        t[ty + i][tx] = src[(size_t)(k0 + ty + i) * N + n0 + tx];
    __syncthreads();
#pragma unroll
    for (int i = 0; i < 32; i += 8) {
        float v = t[tx][ty + i];
        oh[(size_t)(n0 + ty + i) * K + k0 + tx] = __float2half_rn(v);
    }
}
__global__ void conv_up_kernel(const float* __restrict__ uw) {
    int e = blockIdx.z;
    conv_trans_core(uw + (size_t)e * DIM * HUP,
                    g_Bup + (size_t)e * HUP * DIM, DIM, HUP);
}
__global__ void conv_dn_kernel(const float* __restrict__ dw) {
    int e = blockIdx.z;
    conv_trans_core(dw + (size_t)e * HD * DIM,
                    g_Bdn + (size_t)e * DIM * HD, HD, DIM);
}

__device__ __forceinline__ float gelu_exact(float v) {
    return 0.5f * v * (1.f + erff(v * 0.70710678118654752f));
}

// ---------------- fused up GEMM + GLU (fp16, single pass) ----------------
// 512 threads, warp grid 4(m)x4(n); per warp 32x32 of each half.
__global__ void __launch_bounds__(512, 1)
up_gemm_mma(const float* __restrict__ ub) {
    int e = g_tile_e[blockIdx.x];
    if (e < 0) return;
    int base = blockIdx.x * 128;
    int n0a  = blockIdx.y * 128;      // a-half column block; g-half at +HD
    int tid = threadIdx.x, wid = tid >> 5, lane = tid & 31;

    extern __shared__ __align__(1024) char smraw[];
    __shared__ int toks[128];
    uint32_t sb = smem_u32(smraw);

    if (tid < 128) {
        int r = base + tid;
        toks[tid] = (r < g_off[e] + g_count[e]) ? g_row_tok[r] : -1;
    }
    __syncthreads();

    // tiles: 0=A(x fp16), 1=Ba, 2=Bg
    auto load_stage = [&](int s, int k0) {
        uint32_t stg = sb + s * UP_STAGE;
#pragma unroll
        for (int i = 0; i < 6; i++) {
            int ch = tid + i * 512;              // 0..3071
            int tile = ch >> 10, cid = ch & 1023;
            int row = cid >> 3, c = cid & 7;
            uint32_t dst = stg + tile * TILE_B + row * 128 + ((c ^ (row & 7)) << 4);
            int kel = k0 + c * 8;
            const __half* src;
            int z = 16;
            if (tile == 0) {
                int tok = toks[row];
                if (tok < 0) { z = 0; tok = 0; }
                src = g_xh + ((size_t)tok << 10) + kel;
            } else {
                int nrow = n0a + row + ((tile == 2) ? HD : 0);
                src = g_Bup + ((size_t)e << 23) + ((size_t)nrow << 10) + kel;
            }
            cpa16(dst, src, z);
        }
    };

    int mb = (wid & 3) * 32;
    int nb = (wid >> 2) * 32;
    int arow = mb + (lane & 15);
    int aco  = lane >> 4;
    int q = lane >> 3;
    int brow_off = ((q >> 1) << 3) + (lane & 7);
    int bco = q & 1;

    float aacc[2][4][4], gacc[2][4][4];
#pragma unroll
    for (int i = 0; i < 2; i++)
#pragma unroll
        for (int j = 0; j < 4; j++)
#pragma unroll
            for (int r = 0; r < 4; r++) { aacc[i][j][r] = 0.f; gacc[i][j][r] = 0.f; }

    load_stage(0, 0);
    CP_COMMIT();

    const int NC = DIM / 64;   // 16
#pragma unroll 1
    for (int c = 0; c < NC; c++) {
        if (c + 1 < NC) { load_stage((c + 1) & 1, (c + 1) * 64); CP_COMMIT(); CP_WAIT1(); }
        else            { CP_WAIT0(); }
        __syncthreads();
        uint32_t tb = sb + (c & 1) * UP_STAGE;
#pragma unroll
        for (int kk = 0; kk < 4; kk++) {
            int cc = kk * 2;
            uint32_t A2[2][4];
            ldsm4(A2[0], sw_addr(tb, arow,      cc + aco));
            ldsm4(A2[1], sw_addr(tb, arow + 16, cc + aco));
#pragma unroll
            for (int jp = 0; jp < 2; jp++) {
                int brow = nb + jp * 16 + brow_off;
                uint32_t Ba[4], Bg[4];
                ldsm4(Ba, sw_addr(tb + 1*TILE_B, brow, cc + bco));
                ldsm4(Bg, sw_addr(tb + 2*TILE_B, brow, cc + bco));
#pragma unroll
                for (int i = 0; i < 2; i++)
#pragma unroll
                    for (int jj = 0; jj < 2; jj++) {
                        int j = jp * 2 + jj;
                        mma16816(aacc[i][j], A2[i], Ba + jj*2);
                        mma16816(gacc[i][j], A2[i], Bg + jj*2);
                    }
            }
        }
        __syncthreads();
    }

    // ---- epilogue: act = (a+ba) * gelu(g+bg) -> fp16 ----
    int r0 = lane >> 2, cp2 = (lane & 3) * 2;
    const float* ubp = ub + (size_t)e * HUP;
#pragma unroll
    for (int i = 0; i < 2; i++) {
        int rr0 = base + mb + i * 16 + r0;
#pragma unroll
        for (int j = 0; j < 4; j++) {
            int col  = nb + j * 8 + cp2;
            int gcol = n0a + col;
            float ba0 = __ldg(ubp + gcol),      ba1 = __ldg(ubp + gcol + 1);
            float bg0 = __ldg(ubp + HD + gcol), bg1 = __ldg(ubp + HD + gcol + 1);
            float f00 = (aacc[i][j][0] + ba0) * gelu_exact(gacc[i][j][0] + bg0);
            float f01 = (aacc[i][j][1] + ba1) * gelu_exact(gacc[i][j][1] + bg1);
            float f10 = (aacc[i][j][2] + ba0) * gelu_exact(gacc[i][j][2] + bg0);
            float f11 = (aacc[i][j][3] + ba1) * gelu_exact(gacc[i][j][3] + bg1);
            union { __half h[2]; uint32_t u; } P0, P1;
            P0.h[0] = __float2half_rn(f00); P0.h[1] = __float2half_rn(f01);
            P1.h[0] = __float2half_rn(f10); P1.h[1] = __float2half_rn(f11);
            *(uint32_t*)(g_act + (((size_t)rr0)     << 12) + gcol) = P0.u;
            *(uint32_t*)(g_act + (((size_t)rr0 + 8) << 12) + gcol) = P1.u;
        }
    }
}

// ---------------- down GEMM: y = w * (act @ down_w + down_b) ----------------
__global__ void __launch_bounds__(512, 1)
down_gemm_mma(const float* __restrict__ db) {
    int e = g_tile_e[blockIdx.x];
    if (e < 0) return;
    int base = blockIdx.x * 128;
    int n0   = blockIdx.y * 128;
    int tid = threadIdx.x, wid = tid >> 5, lane = tid & 31;

    extern __shared__ __align__(1024) char smraw[];
    uint32_t sb = smem_u32(smraw);

    // tiles: 0=A(act), 1=B
    auto load_stage = [&](int s, int k0) {
        uint32_t stg = sb + s * DN_STAGE;
#pragma unroll
        for (int i = 0; i < 4; i++) {
            int ch = tid + i * 512;              // 0..2047
            int tile = ch >> 10, cid = ch & 1023;
            int row = cid >> 3, c = cid & 7;
            uint32_t dst = stg + tile * TILE_B + row * 128 + ((c ^ (row & 7)) << 4);
            int kel = k0 + c * 8;
            const __half* src;
            if (tile == 0) src = g_act + ((size_t)(base + row) << 12) + kel;
            else           src = g_Bdn + ((size_t)e << 22) + ((size_t)(n0 + row) << 12) + kel;
            cpa16(dst, src, 16);
        }
    };

    int mb = (wid & 3) * 32;
    int nb = (wid >> 2) * 32;
    int arow = mb + (lane & 15);
    int aco  = lane >> 4;
    int q = lane >> 3;
    int brow_off = ((q >> 1) << 3) + (lane & 7);
    int bco = q & 1;

    float acc[2][4][4];
#pragma unroll
    for (int i = 0; i < 2; i++)
#pragma unroll
        for (int j = 0; j < 4; j++)
#pragma unroll
            for (int r = 0; r < 4; r++) acc[i][j][r] = 0.f;

    load_stage(0, 0);
    CP_COMMIT();

    const int NC = HD / 64;   // 64
#pragma unroll 1
    for (int c = 0; c < NC; c++) {
        if (c + 1 < NC) { load_stage((c + 1) & 1, (c + 1) * 64); CP_COMMIT(); CP_WAIT1(); }
        else            { CP_WAIT0(); }
        __syncthreads();
        uint32_t tb = sb + (c & 1) * DN_STAGE;
#pragma unroll
        for (int kk = 0; kk < 4; kk++) {
            int cc = kk * 2;
            uint32_t A2[2][4];
            ldsm4(A2[0], sw_addr(tb, arow,      cc + aco));
            ldsm4(A2[1], sw_addr(tb, arow + 16, cc + aco));
#pragma unroll
            for (int jp = 0; jp < 2; jp++) {
                int brow = nb + jp * 16 + brow_off;
                uint32_t B2[4];
                ldsm4(B2, sw_addr(tb + 1*TILE_B, brow, cc + bco));
#pragma unroll
                for (int i = 0; i < 2; i++)
#pragma unroll
                    for (int jj = 0; jj < 2; jj++) {
                        int j = jp * 2 + jj;
                        mma16816(acc[i][j], A2[i], B2 + jj*2);
                    }
            }
        }
        __syncthreads();
    }

    // ---- epilogue: y[slot] = w * (acc + bias) ----
    int r0 = lane >> 2, cp2 = (lane & 3) * 2;
    int limit = g_off[e] + g_count[e];
    const float* dbp = db + (size_t)e * DIM + n0;
#pragma unroll
    for (int i = 0; i < 2; i++) {
        int rr0 = base + mb + i * 16 + r0;
        int rr1 = rr0 + 8;
        int   s0 = 0, s1 = 0;
        float w0 = 0.f, w1 = 0.f;
        bool v0 = rr0 < limit, v1 = rr1 < limit;
        if (v0) { s0 = g_row_slot[rr0]; w0 = g_row_w[rr0]; }
        if (v1) { s1 = g_row_slot[rr1]; w1 = g_row_w[rr1]; }
#pragma unroll
        for (int j = 0; j < 4; j++) {
            int col = nb + j * 8 + cp2;
            float b0 = __ldg(dbp + col), b1 = __ldg(dbp + col + 1);
            if (v0) {
                float2 v = make_float2(w0 * (acc[i][j][0] + b0), w0 * (acc[i][j][1] + b1));
                *(float2*)(&g_y[(size_t)s0 * DIM + n0 + col]) = v;
            }
            if (v1) {
                float2 v = make_float2(w1 * (acc[i][j][2] + b0), w1 * (acc[i][j][3] + b1));
                *(float2*)(&g_y[(size_t)s1 * DIM + n0 + col]) = v;
            }
        }
    }
}

__global__ void combine_kernel(float* __restrict__ out) {
    int idx = blockIdx.x * blockDim.x + threadIdx.x;    // float4 index
    if (idx >= T_TOK * DIM / 4) return;
    float4 a = *(float4*)(&g_y[(size_t)idx * 4]);
    float4 b = *(float4*)(&g_y[(size_t)(T_TOK * DIM) + (size_t)idx * 4]);
    a.x += b.x; a.y += b.y; a.z += b.z; a.w += b.w;
    ((float4*)out)[idx] = a;
}

// ---------------- launch ----------------
extern "C" void kernel_launch(void* const* d_in, const int* in_sizes, int n_in,
                              void* d_out, int out_size) {
    const float* x  = (const float*)d_in[0];
    const float* rw = (const float*)d_in[1];
    const float* rb = (const float*)d_in[2];
    const float* uw = (const float*)d_in[3];
    const float* ub = (const float*)d_in[4];
    const float* dw = (const float*)d_in[5];
    const float* db = (const float*)d_in[6];
    float* out = (float*)d_out;

    cudaFuncSetAttribute(up_gemm_mma,   cudaFuncAttributeMaxDynamicSharedMemorySize, UP_SMEM);
    cudaFuncSetAttribute(down_gemm_mma, cudaFuncAttributeMaxDynamicSharedMemorySize, DN_SMEM);

    reset_kernel<<<1, 32>>>();
    router_kernel<<<(T_TOK * 32) / 256, 256>>>(x, rw, rb);
    offsets_kernel<<<1, 32>>>();
    scatter_kernel<<<T_TOK / 256, 256>>>();

    convert_x_kernel<<<(T_TOK * DIM / 4 + 255) / 256, 256>>>(x);
    conv_up_kernel<<<dim3(HUP / 32, DIM / 32, NE), dim3(32, 8)>>>(uw);
    conv_dn_kernel<<<dim3(DIM / 32, HD / 32, NE), dim3(32, 8)>>>(dw);

    up_gemm_mma<<<dim3(NTILES_MAX, HD / 128), 512, UP_SMEM>>>(ub);
    down_gemm_mma<<<dim3(NTILES_MAX, DIM / 128), 512, DN_SMEM>>>(db);
    combine_kernel<<<(T_TOK * DIM / 4 + 255) / 256, 256>>>(out);
}

// round 8
// speedup vs baseline: 7.4935x; 1.1306x over previous
#include <cuda_runtime.h>
#include <cuda_fp16.h>
#include <math.h>
#include <stdint.h>

// ---------------- problem constants ----------------
#define T_TOK 8192
#define DIM   1024
#define NE    8
#define HUP   8192
#define HD    4096
#define ROWS_MAX   (2*T_TOK + NE*128)     // 17408
#define NTILES_MAX (ROWS_MAX/128)         // 136

// ---------------- device scratch ----------------
__device__ int   g_count[NE];
__device__ int   g_fill[NE];
__device__ int   g_off[NE];
__device__ int   g_tile_e[NTILES_MAX];
__device__ int   g_topk[T_TOK*2];
__device__ float g_topw[T_TOK*2];
__device__ int   g_row_tok[ROWS_MAX];
__device__ float g_row_w[ROWS_MAX];
__device__ int   g_row_slot[ROWS_MAX];

__device__ __half g_xh[T_TOK*DIM];
__device__ __half g_Bup[67108864];    // [E][N=8192][K=1024] fp16
__device__ __half g_Bdn[33554432];    // [E][N=1024][K=4096] fp16
__device__ __half g_act[71303168];    // [ROWS_MAX][4096] fp16
__device__ float  g_y[16777216];      // [2][T_TOK][DIM]

// ---------------- PTX helpers ----------------
__device__ __forceinline__ uint32_t smem_u32(const void* p) {
    uint32_t a;
    asm("{ .reg .u64 t; cvta.to.shared.u64 t, %1; cvt.u32.u64 %0, t; }" : "=r"(a) : "l"(p));
    return a;
}
__device__ __forceinline__ void cpa16(uint32_t dst, const void* src, int zfill) {
    asm volatile("cp.async.cg.shared.global [%0], [%1], 16, %2;"
                 :: "r"(dst), "l"(src), "r"(zfill));
}
#define CP_COMMIT() asm volatile("cp.async.commit_group;")
#define CP_WAIT1()  asm volatile("cp.async.wait_group 1;")
#define CP_WAIT0()  asm volatile("cp.async.wait_group 0;")

__device__ __forceinline__ void ldsm4(uint32_t* r, uint32_t addr) {
    asm volatile("ldmatrix.sync.aligned.m8n8.x4.shared.b16 {%0,%1,%2,%3}, [%4];"
        : "=r"(r[0]), "=r"(r[1]), "=r"(r[2]), "=r"(r[3]) : "r"(addr));
}
__device__ __forceinline__ void mma16816(float* c, const uint32_t* a, const uint32_t* b) {
    asm volatile("mma.sync.aligned.m16n8k16.row.col.f32.f16.f16.f32 "
        "{%0,%1,%2,%3}, {%4,%5,%6,%7}, {%8,%9}, {%0,%1,%2,%3};"
        : "+f"(c[0]), "+f"(c[1]), "+f"(c[2]), "+f"(c[3])
        : "r"(a[0]), "r"(a[1]), "r"(a[2]), "r"(a[3]), "r"(b[0]), "r"(b[1]));
}
__device__ __forceinline__ uint32_t sw_addr(uint32_t tb, int row, int cc) {
    return tb + row * 128 + ((cc ^ (row & 7)) << 4);
}

#define TILE_B 16384
#define STAGE_B (2*TILE_B)      // A tile + B tile
#define GEMM_SMEM (2*STAGE_B)   // 65536, 2 stages

// ---------------- small kernels ----------------
__global__ void reset_kernel() {
    int i = threadIdx.x;
    if (i < NE) { g_count[i] = 0; g_fill[i] = 0; }
}

__global__ void router_kernel(const float* __restrict__ x,
                              const float* __restrict__ rw,
                              const float* __restrict__ rb) {
    int t    = (blockIdx.x * blockDim.x + threadIdx.x) >> 5;
    int lane = threadIdx.x & 31;
    if (t >= T_TOK) return;
    const float* xr = x + (size_t)t * DIM;
    float acc[NE];
#pragma unroll
    for (int e = 0; e < NE; e++) acc[e] = 0.f;
    for (int d = lane; d < DIM; d += 32) {
        float xv = xr[d];
        const float* w = rw + d * NE;
#pragma unroll
        for (int e = 0; e < NE; e++) acc[e] += xv * __ldg(&w[e]);
    }
#pragma unroll
    for (int o = 16; o > 0; o >>= 1)
#pragma unroll
        for (int e = 0; e < NE; e++)
            acc[e] += __shfl_xor_sync(0xffffffffu, acc[e], o);
    if (lane == 0) {
        float l1 = -1e30f, l2 = -1e30f;
        int i1 = 0, i2 = 0;
#pragma unroll
        for (int e = 0; e < NE; e++) {
            float l = acc[e] + rb[e];
            if (l > l1)      { l2 = l1; i2 = i1; l1 = l; i1 = e; }
            else if (l > l2) { l2 = l; i2 = e; }
        }
        float p2 = 1.f / (1.f + expf(l1 - l2));
        float p1 = 1.f - p2;
        g_topk[2*t+0] = i1;  g_topw[2*t+0] = p1;
        g_topk[2*t+1] = i2;  g_topw[2*t+1] = p2;
        atomicAdd(&g_count[i1], 1);
        atomicAdd(&g_count[i2], 1);
    }
}

__global__ void offsets_kernel() {
    if (threadIdx.x == 0) {
        int tot = 0;
        for (int e = 0; e < NE; e++) {
            g_off[e] = tot;
            int pt = (g_count[e] + 127) >> 7;
            for (int i = 0; i < pt; i++) g_tile_e[tot/128 + i] = e;
            tot += pt * 128;
        }
        for (int i = tot/128; i < NTILES_MAX; i++) g_tile_e[i] = -1;
    }
}

__global__ void scatter_kernel() {
    int t = blockIdx.x * blockDim.x + threadIdx.x;
    if (t >= T_TOK) return;
#pragma unroll
    for (int k = 0; k < 2; k++) {
        int e = g_topk[2*t+k];
        int pos = atomicAdd(&g_fill[e], 1);
        int row = g_off[e] + pos;
        g_row_tok[row]  = t;
        g_row_w[row]    = g_topw[2*t+k];
        g_row_slot[row] = k * T_TOK + t;
    }
}

// x fp32 -> fp16
__global__ void convert_x_kernel(const float* __restrict__ x) {
    int idx = blockIdx.x * blockDim.x + threadIdx.x;       // float4 index
    if (idx >= T_TOK * DIM / 4) return;
    float4 v = *(const float4*)(x + (size_t)idx * 4);
    union { __half h[4]; uint2 u; } H;
    H.h[0] = __float2half_rn(v.x);
    H.h[1] = __float2half_rn(v.y);
    H.h[2] = __float2half_rn(v.z);
    H.h[3] = __float2half_rn(v.w);
    *(uint2*)(g_xh + (size_t)idx * 4) = H.u;
}

// transpose [K,N] fp32 -> [N,K] fp16 (per expert via blockIdx.z)
__device__ __forceinline__ void conv_trans_core(
    const float* __restrict__ src, __half* oh, int K, int N) {
    __shared__ float t[32][33];
    int k0 = blockIdx.y * 32, n0 = blockIdx.x * 32;
    int tx = threadIdx.x, ty = threadIdx.y;
#pragma unroll
    for (int i = 0; i < 32; i += 8)
        t[ty + i][tx] = src[(size_t)(k0 + ty + i) * N + n0 + tx];
    __syncthreads();
#pragma unroll
    for (int i = 0; i < 32; i += 8) {
        float v = t[tx][ty + i];
        oh[(size_t)(n0 + ty + i) * K + k0 + tx] = __float2half_rn(v);
    }
}
__global__ void conv_up_kernel(const float* __restrict__ uw) {
    int e = blockIdx.z;
    conv_trans_core(uw + (size_t)e * DIM * HUP,
                    g_Bup + (size_t)e * HUP * DIM, DIM, HUP);
}
__global__ void conv_dn_kernel(const float* __restrict__ dw) {
    int e = blockIdx.z;
    conv_trans_core(dw + (size_t)e * HD * DIM,
                    g_Bdn + (size_t)e * DIM * HD, HD, DIM);
}

__device__ __forceinline__ float gelu_exact(float v) {
    return 0.5f * v * (1.f + erff(v * 0.70710678118654752f));
}

// ---------------- fused up GEMM + GLU (fp16 single pass) ----------------
// CTA: 128 m x (64 a-cols + 64 g-cols). SMEM B rows interleaved in 32-row
// blocks: [Wa 0:32 | Wg 0:32 | Wa 32:64 | Wg 32:64] so each warp's 64-row
// n-slice holds matched a/g columns (fragment j pairs with j+4).
// 256 threads, warp grid 4(m) x 2(n), warp tile 32m x 64n.
__global__ void __launch_bounds__(256, 2)
up_gemm_mma(const float* __restrict__ ub) {
    int e = g_tile_e[blockIdx.x];
    if (e < 0) return;
    int base = blockIdx.x * 128;
    int n0   = blockIdx.y * 64;       // a-col block base within HD
    int tid = threadIdx.x, wid = tid >> 5, lane = tid & 31;

    extern __shared__ __align__(1024) char smraw[];
    __shared__ int toks[128];
    uint32_t sb = smem_u32(smraw);

    if (tid < 128) {
        int r = base + tid;
        toks[tid] = (r < g_off[e] + g_count[e]) ? g_row_tok[r] : -1;
    }
    __syncthreads();

    // tiles: 0=A(x fp16), 1=B(a/g interleaved)
    auto load_stage = [&](int s, int k0) {
        uint32_t stg = sb + s * STAGE_B;
#pragma unroll
        for (int i = 0; i < 8; i++) {
            int ch = tid + i * 256;              // 0..2047
            int tile = ch >> 10, cid = ch & 1023;
            int row = cid >> 3, c = cid & 7;
            uint32_t dst = stg + tile * TILE_B + row * 128 + ((c ^ (row & 7)) << 4);
            int kel = k0 + c * 8;
            const __half* src;
            int z = 16;
            if (tile == 0) {
                int tok = toks[row];
                if (tok < 0) { z = 0; tok = 0; }
                src = g_xh + ((size_t)tok << 10) + kel;
            } else {
                int blk = row >> 5;
                int nloc = (row & 31) + ((blk >> 1) << 5);
                int grow = n0 + nloc + ((blk & 1) ? HD : 0);
                src = g_Bup + ((size_t)e << 23) + ((size_t)grow << 10) + kel;
            }
            cpa16(dst, src, z);
        }
    };

    int mb = (wid & 3) * 32;
    int wn = wid >> 2;                 // 0,1
    int nbrow = wn * 64;               // warp's smem B row base
    int arow = mb + (lane & 15);
    int aco  = lane >> 4;
    int q = lane >> 3;
    int brow_off = ((q >> 1) << 3) + (lane & 7);
    int bco = q & 1;

    float acc[2][8][4];
#pragma unroll
    for (int i = 0; i < 2; i++)
#pragma unroll
        for (int j = 0; j < 8; j++)
#pragma unroll
            for (int r = 0; r < 4; r++) acc[i][j][r] = 0.f;

    load_stage(0, 0);
    CP_COMMIT();

    const int NC = DIM / 64;   // 16
#pragma unroll 1
    for (int c = 0; c < NC; c++) {
        if (c + 1 < NC) { load_stage((c + 1) & 1, (c + 1) * 64); CP_COMMIT(); CP_WAIT1(); }
        else            { CP_WAIT0(); }
        __syncthreads();
        uint32_t tb = sb + (c & 1) * STAGE_B;
#pragma unroll
        for (int kk = 0; kk < 4; kk++) {
            int cc = kk * 2;
            uint32_t A2[2][4];
            ldsm4(A2[0], sw_addr(tb, arow,      cc + aco));
            ldsm4(A2[1], sw_addr(tb, arow + 16, cc + aco));
            uint32_t Bf[4][4];
#pragma unroll
            for (int jp = 0; jp < 4; jp++)
                ldsm4(Bf[jp], sw_addr(tb + TILE_B, nbrow + jp * 16 + brow_off, cc + bco));
#pragma unroll
            for (int i = 0; i < 2; i++)
#pragma unroll
                for (int jp = 0; jp < 4; jp++)
#pragma unroll
                    for (int jj = 0; jj < 2; jj++)
                        mma16816(acc[i][jp * 2 + jj], A2[i], Bf[jp] + jj * 2);
        }
        __syncthreads();
    }

    // ---- epilogue: act = (a+ba) * gelu(g+bg) -> fp16 ----
    // fragment j in 0..3 = a-cols, j+4 = matching g-cols (same thread).
    int r0 = lane >> 2, cp2 = (lane & 3) * 2;
    const float* ubp = ub + (size_t)e * HUP;
#pragma unroll
    for (int i = 0; i < 2; i++) {
        int rr0 = base + mb + i * 16 + r0;
#pragma unroll
        for (int j = 0; j < 4; j++) {
            int col = n0 + wn * 32 + j * 8 + cp2;   // column within HD
            float ba0 = __ldg(ubp + col),      ba1 = __ldg(ubp + col + 1);
            float bg0 = __ldg(ubp + HD + col), bg1 = __ldg(ubp + HD + col + 1);
            float f00 = (acc[i][j][0] + ba0) * gelu_exact(acc[i][j+4][0] + bg0);
            float f01 = (acc[i][j][1] + ba1) * gelu_exact(acc[i][j+4][1] + bg1);
            float f10 = (acc[i][j][2] + ba0) * gelu_exact(acc[i][j+4][2] + bg0);
            float f11 = (acc[i][j][3] + ba1) * gelu_exact(acc[i][j+4][3] + bg1);
            union { __half h[2]; uint32_t u; } P0, P1;
            P0.h[0] = __float2half_rn(f00); P0.h[1] = __float2half_rn(f01);
            P1.h[0] = __float2half_rn(f10); P1.h[1] = __float2half_rn(f11);
            *(uint32_t*)(g_act + (((size_t)rr0)     << 12) + col) = P0.u;
            *(uint32_t*)(g_act + (((size_t)rr0 + 8) << 12) + col) = P1.u;
        }
    }
}

// ---------------- down GEMM: y = w * (act @ down_w + down_b) ----------------
// 256 threads, warp grid 4(m) x 2(n), warp tile 32m x 64n.
__global__ void __launch_bounds__(256, 2)
down_gemm_mma(const float* __restrict__ db) {
    int e = g_tile_e[blockIdx.x];
    if (e < 0) return;
    int base = blockIdx.x * 128;
    int n0   = blockIdx.y * 128;
    int tid = threadIdx.x, wid = tid >> 5, lane = tid & 31;

    extern __shared__ __align__(1024) char smraw[];
    uint32_t sb = smem_u32(smraw);

    // tiles: 0=A(act), 1=B
    auto load_stage = [&](int s, int k0) {
        uint32_t stg = sb + s * STAGE_B;
#pragma unroll
        for (int i = 0; i < 8; i++) {
            int ch = tid + i * 256;              // 0..2047
            int tile = ch >> 10, cid = ch & 1023;
            int row = cid >> 3, c = cid & 7;
            uint32_t dst = stg + tile * TILE_B + row * 128 + ((c ^ (row & 7)) << 4);
            int kel = k0 + c * 8;
            const __half* src;
            if (tile == 0) src = g_act + ((size_t)(base + row) << 12) + kel;
            else           src = g_Bdn + ((size_t)e << 22) + ((size_t)(n0 + row) << 12) + kel;
            cpa16(dst, src, 16);
        }
    };

    int mb = (wid & 3) * 32;
    int wn = wid >> 2;
    int nbrow = wn * 64;
    int arow = mb + (lane & 15);
    int aco  = lane >> 4;
    int q = lane >> 3;
    int brow_off = ((q >> 1) << 3) + (lane & 7);
    int bco = q & 1;

    float acc[2][8][4];
#pragma unroll
    for (int i = 0; i < 2; i++)
#pragma unroll
        for (int j = 0; j < 8; j++)
#pragma unroll
            for (int r = 0; r < 4; r++) acc[i][j][r] = 0.f;

    load_stage(0, 0);
    CP_COMMIT();

    const int NC = HD / 64;   // 64
#pragma unroll 1
    for (int c = 0; c < NC; c++) {
        if (c + 1 < NC) { load_stage((c + 1) & 1, (c + 1) * 64); CP_COMMIT(); CP_WAIT1(); }
        else            { CP_WAIT0(); }
        __syncthreads();
        uint32_t tb = sb + (c & 1) * STAGE_B;
#pragma unroll
        for (int kk = 0; kk < 4; kk++) {
            int cc = kk * 2;
            uint32_t A2[2][4];
            ldsm4(A2[0], sw_addr(tb, arow,      cc + aco));
            ldsm4(A2[1], sw_addr(tb, arow + 16, cc + aco));
            uint32_t Bf[4][4];
#pragma unroll
            for (int jp = 0; jp < 4; jp++)
                ldsm4(Bf[jp], sw_addr(tb + TILE_B, nbrow + jp * 16 + brow_off, cc + bco));
#pragma unroll
            for (int i = 0; i < 2; i++)
#pragma unroll
                for (int jp = 0; jp < 4; jp++)
#pragma unroll
                    for (int jj = 0; jj < 2; jj++)
                        mma16816(acc[i][jp * 2 + jj], A2[i], Bf[jp] + jj * 2);
        }
        __syncthreads();
    }

    // ---- epilogue: y[slot] = w * (acc + bias) ----
    int r0 = lane >> 2, cp2 = (lane & 3) * 2;
    int limit = g_off[e] + g_count[e];
    const float* dbp = db + (size_t)e * DIM + n0;
#pragma unroll
    for (int i = 0; i < 2; i++) {
        int rr0 = base + mb + i * 16 + r0;
        int rr1 = rr0 + 8;
        int   s0 = 0, s1 = 0;
        float w0 = 0.f, w1 = 0.f;
        bool v0 = rr0 < limit, v1 = rr1 < limit;
        if (v0) { s0 = g_row_slot[rr0]; w0 = g_row_w[rr0]; }
        if (v1) { s1 = g_row_slot[rr1]; w1 = g_row_w[rr1]; }
#pragma unroll
        for (int j = 0; j < 8; j++) {
            int col = wn * 64 + j * 8 + cp2;
            float b0 = __ldg(dbp + col), b1 = __ldg(dbp + col + 1);
            if (v0) {
                float2 v = make_float2(w0 * (acc[i][j][0] + b0), w0 * (acc[i][j][1] + b1));
                *(float2*)(&g_y[(size_t)s0 * DIM + n0 + col]) = v;
            }
            if (v1) {
                float2 v = make_float2(w1 * (acc[i][j][2] + b0), w1 * (acc[i][j][3] + b1));
                *(float2*)(&g_y[(size_t)s1 * DIM + n0 + col]) = v;
            }
        }
    }
}

__global__ void combine_kernel(float* __restrict__ out) {
    int idx = blockIdx.x * blockDim.x + threadIdx.x;    // float4 index
    if (idx >= T_TOK * DIM / 4) return;
    float4 a = *(float4*)(&g_y[(size_t)idx * 4]);
    float4 b = *(float4*)(&g_y[(size_t)(T_TOK * DIM) + (size_t)idx * 4]);
    a.x += b.x; a.y += b.y; a.z += b.z; a.w += b.w;
    ((float4*)out)[idx] = a;
}

// ---------------- launch ----------------
extern "C" void kernel_launch(void* const* d_in, const int* in_sizes, int n_in,
                              void* d_out, int out_size) {
    const float* x  = (const float*)d_in[0];
    const float* rw = (const float*)d_in[1];
    const float* rb = (const float*)d_in[2];
    const float* uw = (const float*)d_in[3];
    const float* ub = (const float*)d_in[4];
    const float* dw = (const float*)d_in[5];
    const float* db = (const float*)d_in[6];
    float* out = (float*)d_out;

    cudaFuncSetAttribute(up_gemm_mma,   cudaFuncAttributeMaxDynamicSharedMemorySize, GEMM_SMEM);
    cudaFuncSetAttribute(down_gemm_mma, cudaFuncAttributeMaxDynamicSharedMemorySize, GEMM_SMEM);

    reset_kernel<<<1, 32>>>();
    router_kernel<<<(T_TOK * 32) / 256, 256>>>(x, rw, rb);
    offsets_kernel<<<1, 32>>>();
    scatter_kernel<<<T_TOK / 256, 256>>>();

    convert_x_kernel<<<(T_TOK * DIM / 4 + 255) / 256, 256>>>(x);
    conv_up_kernel<<<dim3(HUP / 32, DIM / 32, NE), dim3(32, 8)>>>(uw);
    conv_dn_kernel<<<dim3(DIM / 32, HD / 32, NE), dim3(32, 8)>>>(dw);

    up_gemm_mma<<<dim3(NTILES_MAX, HD / 64), 256, GEMM_SMEM>>>(ub);
    down_gemm_mma<<<dim3(NTILES_MAX, DIM / 128), 256, GEMM_SMEM>>>(db);
    combine_kernel<<<(T_TOK * DIM / 4 + 255) / 256, 256>>>(out);
}